// round 1
// baseline (speedup 1.0000x reference)
#include <cuda_runtime.h>
#include <math.h>

#define B_ 4
#define S_ 4096
#define D_ 4096
#define H_ 128
#define E_ 8
#define M_ (B_*S_)

#define MT 128      // M tile per CTA
#define KC 32       // K chunk
#define XPAD 132    // padded row length for transposed X tile (16B-aligned rows, reduced bank conflicts)
#define NTHREADS 256

// -------- device globals (scratch; no allocation allowed) --------
__device__ float g_hpart[B_][32][H_];
__device__ float g_task_w[B_][E_];
__device__ float g_alpha;

// ---------------- packed f32x2 helpers ----------------
__device__ __forceinline__ unsigned long long pack_dup(float x) {
    unsigned long long r;
    unsigned u = __float_as_uint(x);
    asm("mov.b64 %0, {%1, %1};" : "=l"(r) : "r"(u));
    return r;
}
__device__ __forceinline__ void fma2(unsigned long long& c, unsigned long long a, unsigned long long b) {
    asm("fma.rn.f32x2 %0, %1, %2, %0;" : "+l"(c) : "l"(a), "l"(b));
}
__device__ __forceinline__ float2 unpack2(unsigned long long c) {
    unsigned lo, hi;
    asm("mov.b64 {%0, %1}, %2;" : "=r"(lo), "=r"(hi) : "l"(c));
    return make_float2(__uint_as_float(lo), __uint_as_float(hi));
}

// ---------------- task router: partial h ----------------
// grid (32, B_), 128 threads. block (c,b): h-partials over d in [c*128, c*128+128)
__global__ void task_partial_kernel(const float* __restrict__ task,
                                    const float* __restrict__ TW1) {
    int c = blockIdx.x, b = blockIdx.y, t = threadIdx.x;
    const float* tp = task + (size_t)b * D_ + c * 128;
    const float* w  = TW1 + (size_t)(c * 128) * H_ + t;
    float acc = 0.f;
#pragma unroll 8
    for (int d = 0; d < 128; d++)
        acc += tp[d] * w[(size_t)d * H_];
    g_hpart[b][c][t] = acc;
}

// ---------------- task router: finish ----------------
// 1 block, 128 threads
__global__ void task_finish_kernel(const float* __restrict__ Tb1,
                                   const float* __restrict__ TW2,
                                   const float* __restrict__ Tb2,
                                   const float* __restrict__ alpha) {
    __shared__ float hsm[B_][H_];
    __shared__ float lsm[B_][E_];
    int t = threadIdx.x;
#pragma unroll
    for (int b = 0; b < B_; b++) {
        float acc = Tb1[t];
#pragma unroll
        for (int c = 0; c < 32; c++) acc += g_hpart[b][c][t];
        hsm[b][t] = fmaxf(acc, 0.f);
    }
    __syncthreads();
    if (t < B_ * E_) {
        int b = t / E_, e = t % E_;
        float acc = Tb2[e];
#pragma unroll 8
        for (int j = 0; j < H_; j++) acc += hsm[b][j] * TW2[j * E_ + e];
        lsm[b][e] = acc;
    }
    __syncthreads();
    if (t < B_) {
        float mx = lsm[t][0];
#pragma unroll
        for (int e = 1; e < E_; e++) mx = fmaxf(mx, lsm[t][e]);
        float ex[E_], s = 0.f;
#pragma unroll
        for (int e = 0; e < E_; e++) { ex[e] = expf(lsm[t][e] - mx); s += ex[e]; }
        float inv = 1.f / s;
#pragma unroll
        for (int e = 0; e < E_; e++) g_task_w[t][e] = ex[e] * inv;
    }
    if (t == 0) g_alpha = 1.f / (1.f + expf(-alpha[0]));
}

// ---------------- main fused kernel ----------------
// grid 128 CTAs, 256 threads. Tile: 128 rows x 128 cols (full H), K-loop of 32,
// double-buffered SMEM, 8x8 per-thread microtile with packed f32x2 FMAs.
extern __shared__ float smem_dyn[];

__global__ __launch_bounds__(NTHREADS, 1)
void main_fused_kernel(const float* __restrict__ X,
                       const float* __restrict__ W1,
                       const float* __restrict__ b1,
                       const float* __restrict__ W2,
                       const float* __restrict__ b2,
                       float* __restrict__ out) {
    float* Xs  = smem_dyn;                    // [2][KC][XPAD], transposed (k-major)
    float* Ws  = Xs + 2 * KC * XPAD;          // [2][KC][H_]
    float* W2s = Ws + 2 * KC * H_;            // [H_][E_]
    float* b2s = W2s + H_ * E_;               // [E_]

    const int tid = threadIdx.x;
    const int tx = tid & 15, ty = tid >> 4;
    const int m0 = blockIdx.x * MT;

    // stage W2/b2 once
    for (int i = tid; i < H_ * E_; i += NTHREADS) W2s[i] = W2[i];
    if (tid < E_) b2s[tid] = b2[tid];

    unsigned long long acc[4][8];
#pragma unroll
    for (int i2 = 0; i2 < 4; i2++)
#pragma unroll
        for (int j = 0; j < 8; j++) acc[i2][j] = 0ULL;

    float4 xr[4], wr[4];

    // global->reg loaders (chunk ch)
    auto load_g = [&](int ch) {
        const int k0 = ch * KC;
#pragma unroll
        for (int l = 0; l < 4; l++) {
            int q  = tid + NTHREADS * l;
            int m  = q >> 3, kq = q & 7;
            xr[l] = *(const float4*)(X + (size_t)(m0 + m) * D_ + k0 + kq * 4);
            int kw = q >> 5, nq = q & 31;
            wr[l] = *(const float4*)(W1 + (size_t)(k0 + kw) * H_ + nq * 4);
        }
    };
    auto store_s = [&](int buf) {
        float* Xb = Xs + buf * KC * XPAD;
        float* Wb = Ws + buf * KC * H_;
#pragma unroll
        for (int l = 0; l < 4; l++) {
            int q = tid + NTHREADS * l;
            int m = q >> 3, kq = q & 7;
            Xb[(kq * 4 + 0) * XPAD + m] = xr[l].x;
            Xb[(kq * 4 + 1) * XPAD + m] = xr[l].y;
            Xb[(kq * 4 + 2) * XPAD + m] = xr[l].z;
            Xb[(kq * 4 + 3) * XPAD + m] = xr[l].w;
            int kw = q >> 5, nq = q & 31;
            *(float4*)(Wb + kw * H_ + nq * 4) = wr[l];
        }
    };

    const int NCH = D_ / KC;  // 128
    load_g(0);
    store_s(0);

    for (int ch = 0; ch < NCH; ch++) {
        int cur = ch & 1;
        __syncthreads();
        if (ch + 1 < NCH) load_g(ch + 1);

        const float* Xb = Xs + cur * KC * XPAD;
        const float* Wb = Ws + cur * KC * H_;
#pragma unroll
        for (int kk = 0; kk < KC; kk++) {
            ulonglong2 a01 = *(const ulonglong2*)(Xb + kk * XPAD + ty * 8);
            ulonglong2 a23 = *(const ulonglong2*)(Xb + kk * XPAD + ty * 8 + 4);
            float4 bv0 = *(const float4*)(Wb + kk * H_ + tx * 8);
            float4 bv1 = *(const float4*)(Wb + kk * H_ + tx * 8 + 4);
            unsigned long long aa0 = a01.x, aa1 = a01.y, aa2 = a23.x, aa3 = a23.y;
            unsigned long long bb[8];
            bb[0] = pack_dup(bv0.x); bb[1] = pack_dup(bv0.y);
            bb[2] = pack_dup(bv0.z); bb[3] = pack_dup(bv0.w);
            bb[4] = pack_dup(bv1.x); bb[5] = pack_dup(bv1.y);
            bb[6] = pack_dup(bv1.z); bb[7] = pack_dup(bv1.w);
#pragma unroll
            for (int j = 0; j < 8; j++) {
                fma2(acc[0][j], aa0, bb[j]);
                fma2(acc[1][j], aa1, bb[j]);
                fma2(acc[2][j], aa2, bb[j]);
                fma2(acc[3][j], aa3, bb[j]);
            }
        }
        if (ch + 1 < NCH) store_s(cur ^ 1);
    }

    // ---- epilogue: bias + relu ----
    float b1v[8];
#pragma unroll
    for (int j = 0; j < 8; j++) b1v[j] = __ldg(b1 + tx * 8 + j);

    float h[8][8];
#pragma unroll
    for (int i2 = 0; i2 < 4; i2++)
#pragma unroll
        for (int j = 0; j < 8; j++) {
            float2 v = unpack2(acc[i2][j]);
            h[2 * i2 + 0][j] = fmaxf(v.x + b1v[j], 0.f);
            h[2 * i2 + 1][j] = fmaxf(v.y + b1v[j], 0.f);
        }

    // ---- partial logits: pl[e][i] over this thread's 8 h-columns ----
    float pl[E_][8];
#pragma unroll
    for (int e = 0; e < E_; e++)
#pragma unroll
        for (int i = 0; i < 8; i++) pl[e][i] = 0.f;

#pragma unroll
    for (int j = 0; j < 8; j++) {
        int col = tx * 8 + j;
#pragma unroll
        for (int e = 0; e < E_; e++) {
            float w = W2s[col * E_ + e];
#pragma unroll
            for (int i = 0; i < 8; i++) pl[e][i] += h[i][j] * w;
        }
    }

    // ---- reduce over the 16 tx-lanes (half-warp butterfly) ----
#pragma unroll
    for (int off = 8; off >= 1; off >>= 1)
#pragma unroll
        for (int e = 0; e < E_; e++)
#pragma unroll
            for (int i = 0; i < 8; i++)
                pl[e][i] += __shfl_xor_sync(0xffffffffu, pl[e][i], off);

    // ---- per-row routing math (one lane per 8 rows) ----
    if (tx == 0) {
        const float a = g_alpha;
        const float oma = 1.f - a;
#pragma unroll
        for (int i = 0; i < 8; i++) {
            int row = m0 + ty * 8 + i;
            int bb  = row >> 12;  // row / S_
            float l[E_];
            float mx = -3.4e38f;
#pragma unroll
            for (int e = 0; e < E_; e++) {
                l[e] = pl[e][i] + b2s[e];
                mx = fmaxf(mx, l[e]);
            }
            float r[E_], s = 0.f;
#pragma unroll
            for (int e = 0; e < E_; e++) { r[e] = expf(l[e] - mx); s += r[e]; }
            float inv = 1.f / s;
#pragma unroll
            for (int e = 0; e < E_; e++) r[e] = oma * r[e] * inv + a * g_task_w[bb][e];

            // top-2 (strict > keeps lowest index on ties, matching jax top_k)
            int i1 = 0; float v1 = r[0];
#pragma unroll
            for (int e = 1; e < E_; e++) if (r[e] > v1) { v1 = r[e]; i1 = e; }
            int isec = (i1 == 0) ? 1 : 0; float v2 = r[isec];
#pragma unroll
            for (int e = 0; e < E_; e++)
                if (e != i1 && e != isec && r[e] > v2) { v2 = r[e]; isec = e; }

            float e2  = expf(v2 - v1);
            float den = 1.f / (1.f + e2);
            float o[E_];
#pragma unroll
            for (int e = 0; e < E_; e++) o[e] = 0.f;
            o[i1]   = den;
            o[isec] = e2 * den;

            float4* op = (float4*)(out + (size_t)row * E_);
            op[0] = make_float4(o[0], o[1], o[2], o[3]);
            op[1] = make_float4(o[4], o[5], o[6], o[7]);
        }
    }
}

// ---------------- launch ----------------
extern "C" void kernel_launch(void* const* d_in, const int* in_sizes, int n_in,
                              void* d_out, int out_size) {
    const float* X     = (const float*)d_in[0];
    const float* task  = (const float*)d_in[1];
    const float* W1    = (const float*)d_in[2];
    const float* b1    = (const float*)d_in[3];
    const float* W2    = (const float*)d_in[4];
    const float* b2    = (const float*)d_in[5];
    const float* TW1   = (const float*)d_in[6];
    const float* Tb1   = (const float*)d_in[7];
    const float* TW2   = (const float*)d_in[8];
    const float* Tb2   = (const float*)d_in[9];
    const float* alpha = (const float*)d_in[10];
    float* out = (float*)d_out;

    const int smem_bytes = (2 * KC * XPAD + 2 * KC * H_ + H_ * E_ + E_) * (int)sizeof(float);
    cudaFuncSetAttribute(main_fused_kernel,
                         cudaFuncAttributeMaxDynamicSharedMemorySize, smem_bytes);

    task_partial_kernel<<<dim3(32, B_), 128>>>(task, TW1);
    task_finish_kernel<<<1, 128>>>(Tb1, TW2, Tb2, alpha);
    main_fused_kernel<<<M_ / MT, NTHREADS, smem_bytes>>>(X, W1, b1, W2, b2, out);
}